// round 7
// baseline (speedup 1.0000x reference)
#include <cuda_runtime.h>
#include <cstdint>

// Problem constants
#define NN 2
#define CC 12
#define AA 5
#define HH 256
#define HP 512
#define NIMG (NN*CC*AA)         // 120
#define NPIX (HP*HP)            // 262144
#define CHUNK 6                 // (n,c) pairs per chunk
#define NCHUNK ((NN*CC)/CHUNK)  // 4
#define IMGC (CHUNK*AA)         // 30 images per chunk

#define SZ_X ((long)NN*AA*HH*HH)   // 655360
#define SZ_M ((long)CC*HH*HH)      // 786432
#define SZ_K ((long)AA*AA*HP*HP)   // 6553600

// Scratch (__device__ globals; 189MB total — 377MB failed module load)
__device__ float2 g_bufA[(size_t)NIMG * HH * HP];   // 126MB: [img][row 256][w 512]
__device__ float2 g_bufC[(size_t)IMGC * HP * HP];   // 63MB:  [local img 30][h 512][w 512]

__device__ __forceinline__ int brev9(int i) { return (int)(__brev((unsigned)i) >> 23); }

__device__ __forceinline__ float gld(const float* p, size_t idx, int str, int sz) {
    size_t last = idx * (size_t)str + (size_t)(str - 1);
    return (last < (size_t)sz) ? p[idx * (size_t)str] : 0.0f;
}

__device__ __forceinline__ void bfly(float2* s, int stride, int col, int bf,
                                     int stage, const float2* tw, float isign) {
    int half = 1 << (stage - 1);
    int j = bf & (half - 1);
    int i0 = ((bf ^ j) << 1) + j;
    int i1 = i0 + half;
    float2 w = tw[j << (9 - stage)];
    w.y *= isign;
    float2 A = s[i0 * stride + col];
    float2 B = s[i1 * stride + col];
    float2 t = make_float2(B.x * w.x - B.y * w.y, B.x * w.y + B.y * w.x);
    s[i0 * stride + col] = make_float2(A.x + t.x, A.y + t.y);
    s[i1 * stride + col] = make_float2(A.x - t.x, A.y - t.y);
}

// ---------------------------------------------------------------------------
// F1: row FFTs of padded (x * mps) rows. One block = one (img,row).
// ---------------------------------------------------------------------------
__global__ void __launch_bounds__(256)
k_f1(const float* __restrict__ xr, const float* __restrict__ xi, int xs, int xsz,
     const float* __restrict__ mr, const float* __restrict__ mi, int ms, int msz) {
    __shared__ float2 s[512];
    __shared__ float2 tw[256];
    int tid = threadIdx.x;
    { float sv, cv; sincospif(-(float)tid / 256.0f, &sv, &cv); tw[tid] = make_float2(cv, sv); }

    int blk = blockIdx.x;
    int row = blk & 255;
    int img = blk >> 8;                 // (n*12+c)*5+a
    int a = img % AA;
    int nc = img / AA;
    int c = nc % CC;
    int n = nc / CC;

    size_t xoff = ((size_t)(n * AA + a) * HH + row) * HH;
    size_t moff = ((size_t)c * HH + row) * HH;

    #pragma unroll
    for (int k = 0; k < 2; k++) {
        int pw = tid + k * 256;
        float2 v = make_float2(0.f, 0.f);
        if (pw >= 128 && pw < 384) {
            int iw = pw - 128;
            float ar = gld(xr, xoff + iw, xs, xsz);
            float ai = gld(xi, xoff + iw, xs, xsz);
            float br = gld(mr, moff + iw, ms, msz);
            float bi = gld(mi, moff + iw, ms, msz);
            v = make_float2(ar * br - ai * bi, ar * bi + ai * br);
        }
        s[brev9(pw)] = v;
    }
    __syncthreads();
    #pragma unroll
    for (int st = 1; st <= 9; st++) {
        bfly(s, 1, 0, tid, st, tw, 1.0f);
        __syncthreads();
    }
    float2* out = g_bufA + ((size_t)img * HH + row) * HP;
    out[tid] = s[tid];
    out[tid + 256] = s[tid + 256];
}

// ---------------------------------------------------------------------------
// F2 (chunked): column FFTs of 30 images; zero-embed rows 128..383.
// ---------------------------------------------------------------------------
__global__ void __launch_bounds__(256)
k_f2c(int chunk) {
    __shared__ float2 s[512 * 9];
    __shared__ float2 tw[256];
    int tid = threadIdx.x;
    { float sv, cv; sincospif(-(float)tid / 256.0f, &sv, &cv); tw[tid] = make_float2(cv, sv); }

    int blk = blockIdx.x;
    int tile = blk & 63;
    int l = blk >> 6;                   // local image 0..29
    int img = chunk * IMGC + l;
    int w0 = tile * 8;

    for (int i = tid; i < 512 * 9; i += 256) s[i] = make_float2(0.f, 0.f);
    __syncthreads();

    const float2* in = g_bufA + (size_t)img * HH * HP + w0;
    for (int idx = tid; idx < 256 * 8; idx += 256) {
        int r = idx >> 3, c = idx & 7;
        s[brev9(r + 128) * 9 + c] = in[(size_t)r * HP + c];
    }
    __syncthreads();

    #pragma unroll
    for (int st = 1; st <= 9; st++) {
        int col = tid & 7, lane = tid >> 3;
        #pragma unroll
        for (int k = 0; k < 8; k++) bfly(s, 9, col, lane + k * 32, st, tw, 1.0f);
        __syncthreads();
    }

    float2* out = g_bufC + (size_t)l * NPIX + w0;
    const float sc = 1.0f / 512.0f;
    for (int idx = tid; idx < 512 * 8; idx += 256) {
        int r = idx >> 3, c = idx & 7;
        float2 v = s[r * 9 + c];
        out[(size_t)r * HP + c] = make_float2(v.x * sc, v.y * sc);
    }
}

// ---------------------------------------------------------------------------
// Mix (chunked): in-place 5x5 complex mixing per pixel for 6 (n,c) pairs.
// ---------------------------------------------------------------------------
__global__ void __launch_bounds__(256)
k_mixc(const float* __restrict__ kr, const float* __restrict__ ki, int ks, int ksz) {
    size_t p = (size_t)blockIdx.x * 256 + threadIdx.x;   // 0..262143
    float2 K[5][5];
    #pragma unroll
    for (int b = 0; b < 5; b++)
        #pragma unroll
        for (int a = 0; a < 5; a++) {
            size_t o = (size_t)(b * 5 + a) * NPIX + p;
            K[b][a] = make_float2(gld(kr, o, ks, ksz), gld(ki, o, ks, ksz));
        }
    #pragma unroll 1
    for (int j = 0; j < CHUNK; j++) {
        float2* base = g_bufC + (size_t)(j * 5) * NPIX + p;
        float2 F[5];
        #pragma unroll
        for (int a = 0; a < 5; a++) F[a] = base[(size_t)a * NPIX];
        #pragma unroll
        for (int b = 0; b < 5; b++) {
            float2 acc = make_float2(0.f, 0.f);
            #pragma unroll
            for (int a = 0; a < 5; a++) {
                acc.x += K[b][a].x * F[a].x - K[b][a].y * F[a].y;
                acc.y += K[b][a].x * F[a].y + K[b][a].y * F[a].x;
            }
            base[(size_t)b * NPIX] = acc;
        }
    }
}

// ---------------------------------------------------------------------------
// I1 (chunked): column inverse FFTs; keep rows 128..383. g_bufC -> g_bufA.
// ---------------------------------------------------------------------------
__global__ void __launch_bounds__(256)
k_i1c(int chunk) {
    __shared__ float2 s[512 * 9];
    __shared__ float2 tw[256];
    int tid = threadIdx.x;
    { float sv, cv; sincospif(-(float)tid / 256.0f, &sv, &cv); tw[tid] = make_float2(cv, sv); }

    int blk = blockIdx.x;
    int tile = blk & 63;
    int l = blk >> 6;
    int img = chunk * IMGC + l;
    int w0 = tile * 8;

    const float2* in = g_bufC + (size_t)l * NPIX + w0;
    for (int idx = tid; idx < 512 * 8; idx += 256) {
        int r = idx >> 3, c = idx & 7;
        s[brev9(r) * 9 + c] = in[(size_t)r * HP + c];
    }
    __syncthreads();

    #pragma unroll
    for (int st = 1; st <= 9; st++) {
        int col = tid & 7, lane = tid >> 3;
        #pragma unroll
        for (int k = 0; k < 8; k++) bfly(s, 9, col, lane + k * 32, st, tw, -1.0f);
        __syncthreads();
    }

    float2* out = g_bufA + (size_t)img * HH * HP + w0;
    for (int idx = tid; idx < 256 * 8; idx += 256) {
        int r = idx >> 3, c = idx & 7;
        out[(size_t)r * HP + c] = s[(r + 128) * 9 + c];
    }
}

// ---------------------------------------------------------------------------
// I2: row inverse FFTs on cropped rows; crop cols, *conj(mps), sum over c.
// Output: REAL PART plane (out_size == 655360). If the buffer is twice that,
// also write the imag plane at offset SZ_X (planar layout).
// ---------------------------------------------------------------------------
__global__ void __launch_bounds__(256)
k_i2(const float* __restrict__ mr, const float* __restrict__ mi, int ms, int msz,
     float* __restrict__ out, long out_floats) {
    __shared__ float2 s[512];
    __shared__ float2 tw[256];
    int tid = threadIdx.x;
    { float sv, cv; sincospif(-(float)tid / 256.0f, &sv, &cv); tw[tid] = make_float2(cv, sv); }

    int blk = blockIdx.x;
    int row = blk & 255;
    int nb = blk >> 8;
    int b = nb % AA;
    int n = nb / AA;

    float2 acc = make_float2(0.f, 0.f);
    for (int c = 0; c < CC; c++) {
        int img = (n * CC + c) * AA + b;
        const float2* in = g_bufA + ((size_t)img * HH + row) * HP;
        __syncthreads();   // protect shared reuse across c iterations
        s[brev9(tid)] = in[tid];
        s[brev9(tid + 256)] = in[tid + 256];
        __syncthreads();
        #pragma unroll
        for (int st = 1; st <= 9; st++) {
            bfly(s, 1, 0, tid, st, tw, -1.0f);
            __syncthreads();
        }
        float2 v = s[tid + 128];
        size_t mo = ((size_t)c * HH + row) * HH + tid;
        float m_r = gld(mr, mo, ms, msz);
        float m_i = gld(mi, mo, ms, msz);
        acc.x += v.x * m_r + v.y * m_i;     // v * conj(m)
        acc.y += v.y * m_r - v.x * m_i;
    }
    const float sc = 4.0f / 512.0f;   // OVERSAMP^2 * (1/512 ifft ortho)
    size_t o = ((size_t)(n * AA + b) * HH + row) * HH + tid;
    if ((long)o < out_floats) out[o] = acc.x * sc;            // real plane
    if ((long)(SZ_X + o) < out_floats) out[SZ_X + o] = acc.y * sc;  // imag (only if room)
}

// ---------------------------------------------------------------------------
// Input resolver (matches element- or byte-count sizes; first in class = real)
// ---------------------------------------------------------------------------
static void pick(void* const* d_in, const int* in_sizes, int n_in, long S,
                 int pos_split, const float** re, const float** im,
                 int* str, int* sz) {
    int idx[2] = {-1, -1};
    int cnt = 0;
    long matched = S;
    for (int i = 0; i < n_in; i++) {
        long v = (long)in_sizes[i];
        if (v == S || v == 2 * S || v == 4 * S || v == 8 * S) {
            if (cnt < 2) { idx[cnt] = i; matched = v; }
            cnt++;
        }
    }
    if (cnt >= 2) {                       // split planes: first=real, second=imag
        *re = (const float*)d_in[idx[0]];
        *im = (const float*)d_in[idx[1]];
        *str = 1; *sz = (int)matched;
    } else if (cnt == 1) {                // interleaved complex
        *re = (const float*)d_in[idx[0]];
        *im = *re + 1;
        *str = 2; *sz = (int)matched;
    } else {                              // positional fallback (dict order: r, i)
        int p0 = (pos_split < n_in) ? pos_split : 0;
        int p1 = (pos_split + 1 < n_in) ? pos_split + 1 : p0;
        *re = (const float*)d_in[p0];
        *im = (const float*)d_in[p1];
        *str = 1; *sz = (int)S;
    }
}

extern "C" void kernel_launch(void* const* d_in, const int* in_sizes, int n_in,
                              void* d_out, int out_size) {
    const float *xr, *xi, *mr, *mi, *kr, *ki;
    int xs, ms, ks, xsz, msz, ksz;
    // dict-order positional fallbacks: x @0-1, mps @2-3, kernels @4-5
    pick(d_in, in_sizes, n_in, SZ_X, 0, &xr, &xi, &xs, &xsz);
    pick(d_in, in_sizes, n_in, SZ_M, 2, &mr, &mi, &ms, &msz);
    pick(d_in, in_sizes, n_in, SZ_K, 4, &kr, &ki, &ks, &ksz);
    float* out = (float*)d_out;

    k_f1<<<NIMG * 256, 256>>>(xr, xi, xs, xsz, mr, mi, ms, msz);
    for (int ch = 0; ch < NCHUNK; ch++) {
        k_f2c<<<IMGC * 64, 256>>>(ch);
        k_mixc<<<NPIX / 256, 256>>>(kr, ki, ks, ksz);
        k_i1c<<<IMGC * 64, 256>>>(ch);
    }
    k_i2<<<NN * AA * 256, 256>>>(mr, mi, ms, msz, out, (long)out_size);
}

// round 9
// speedup vs baseline: 1.2440x; 1.2440x over previous
#include <cuda_runtime.h>
#include <cstdint>

#define NN 2
#define CC 12
#define AA 5
#define HH 256
#define HP 512
#define NIMG (NN*CC*AA)         // 120
#define NPIX (HP*HP)            // 262144

#define SZ_X ((long)NN*AA*HH*HH)   // 655360
#define SZ_M ((long)CC*HH*HH)      // 786432
#define SZ_K ((long)AA*AA*HP*HP)   // 6553600

// Scratch: 126MB + 52.4MB = 178.4MB (< ~190MB module limit found in R1-R4)
__device__ float2 g_bufA[(size_t)NIMG * HH * HP];     // [img][row 256][w 512]
__device__ float2 g_kT[(size_t)NPIX * 25];            // [(h*512+w)][b*5+a]

__device__ __forceinline__ int brev9(int i) { return (int)(__brev((unsigned)i) >> 23); }
__device__ __forceinline__ int swz(int i)   { return i ^ ((i >> 3) & 7); }

// ---------------------------------------------------------------------------
// Radix-8 register phase: 3 radix-2 stages on 8 points idx = base + m*str,
// str = 8^p. dif=false: DIT ascending (stages 3p+1..3p+3).
// dif=true:  DIF descending (stages 3p+3..3p+1).
// tw[t] = exp(-i*pi*t/256). isign=+1 keeps the NEGATIVE exponent (forward,
// numpy convention); isign=-1 conjugates (inverse).
// ---------------------------------------------------------------------------
__device__ __forceinline__ void reg_fft_phase(float2* a, int p, int lane,
                                              const float2* tw, float isign, bool dif) {
    int str, base;
    if (p == 0)      { str = 1;  base = lane << 3; }
    else if (p == 1) { str = 8;  base = ((lane >> 3) << 6) | (lane & 7); }
    else             { str = 64; base = lane; }
    int b_lo = base & (str - 1);

    float2 r[8];
    #pragma unroll
    for (int m = 0; m < 8; m++) r[m] = a[swz(base + m * str)];

    #pragma unroll
    for (int ss = 0; ss < 3; ss++) {
        int sub = dif ? (2 - ss) : ss;
        int s = 3 * p + sub + 1;          // global stage 1..9
        int half_m = 1 << sub;
        #pragma unroll
        for (int q = 0; q < 4; q++) {
            int jm = q & (half_m - 1);
            int m0 = ((q ^ jm) << 1) + jm;
            int m1 = m0 + half_m;
            int j = jm * str + b_lo;
            float2 w = tw[(j << (9 - s)) & 255];
            w.y *= isign;
            float2 A = r[m0], B = r[m1];
            if (!dif) {
                float2 t = make_float2(B.x * w.x - B.y * w.y, B.x * w.y + B.y * w.x);
                r[m0] = make_float2(A.x + t.x, A.y + t.y);
                r[m1] = make_float2(A.x - t.x, A.y - t.y);
            } else {
                float2 d = make_float2(A.x - B.x, A.y - B.y);
                r[m0] = make_float2(A.x + B.x, A.y + B.y);
                r[m1] = make_float2(d.x * w.x - d.y * w.y, d.x * w.y + d.y * w.x);
            }
        }
    }
    #pragma unroll
    for (int m = 0; m < 8; m++) a[swz(base + m * str)] = r[m];
}

// ---------------------------------------------------------------------------
// k_tr: transpose kernels into point-major layout kT[(h*512+w)][25]
// ---------------------------------------------------------------------------
__global__ void __launch_bounds__(256)
k_tr(const float* __restrict__ kr, const float* __restrict__ ki) {
    size_t p = (size_t)blockIdx.x * 256 + threadIdx.x;   // 0..NPIX-1
    float2* dst = g_kT + p * 25;
    #pragma unroll
    for (int ba = 0; ba < 25; ba++)
        dst[ba] = make_float2(kr[(size_t)ba * NPIX + p], ki[(size_t)ba * NPIX + p]);
}

// ---------------------------------------------------------------------------
// k_f1: row FFTs of padded x*mps. Block = (img, 4 rows), 256 thr, radix-8.
// Natural-order output (DIT with bit-rev input placement). FORWARD: isign=+1.
// ---------------------------------------------------------------------------
__global__ void __launch_bounds__(256)
k_f1(const float* __restrict__ xr, const float* __restrict__ xi,
     const float* __restrict__ mr, const float* __restrict__ mi) {
    __shared__ float2 d[4][512];
    __shared__ float2 tw[256];
    int tid = threadIdx.x;
    { float sv, cv; sincospif(-(float)tid / 256.0f, &sv, &cv); tw[tid] = make_float2(cv, sv); }

    int img = blockIdx.x >> 6;
    int rg = blockIdx.x & 63;
    int row0 = rg * 4;
    int a = img % AA, nc = img / AA, c = nc % CC, n = nc / CC;

    for (int i = tid; i < 4 * 512; i += 256) ((float2*)d)[i] = make_float2(0.f, 0.f);
    __syncthreads();

    for (int i = tid; i < 4 * 256; i += 256) {
        int r = i >> 8, iw = i & 255;
        size_t xo = ((size_t)(n * AA + a) * HH + row0 + r) * HH + iw;
        size_t mo = ((size_t)c * HH + row0 + r) * HH + iw;
        float ar = xr[xo], ai = xi[xo], br = mr[mo], bi = mi[mo];
        d[r][swz(brev9(128 + iw))] = make_float2(ar * br - ai * bi, ar * bi + ai * br);
    }
    __syncthreads();

    int row = tid >> 6, lane = tid & 63;
    reg_fft_phase(d[row], 0, lane, tw, 1.f, false); __syncthreads();
    reg_fft_phase(d[row], 1, lane, tw, 1.f, false); __syncthreads();
    reg_fft_phase(d[row], 2, lane, tw, 1.f, false); __syncthreads();

    float2* out = g_bufA + ((size_t)img * HH + row0) * HP;
    for (int i = tid; i < 4 * 512; i += 256) {
        int r = i >> 9, t = i & 511;
        out[(size_t)r * HP + t] = d[r][swz(t)];
    }
}

// ---------------------------------------------------------------------------
// k_fused: per (n,c) and 2-column tile: forward column FFT (zero-embed rows
// 128..383), 5x5 mix at natural (h,w) via kT, inverse column FFT, cropped
// in-place write-back. Forward isign=+1, inverse isign=-1.
// ---------------------------------------------------------------------------
__global__ void __launch_bounds__(320)
k_fused() {
    __shared__ float2 d[10][512];     // [arr*2+col][512]
    __shared__ float2 tw[256];
    int tid = threadIdx.x;
    if (tid < 256) { float sv, cv; sincospif(-(float)tid / 256.0f, &sv, &cv); tw[tid] = make_float2(cv, sv); }

    int bid = blockIdx.x;
    int nc = bid % (NN * CC);
    int wt = bid / (NN * CC);
    int w0 = wt * 2;

    for (int i = tid; i < 10 * 512; i += 320) ((float2*)d)[i] = make_float2(0.f, 0.f);
    __syncthreads();

    // load 5 images x 256 rows x 2 cols, scatter to brev9(row+128)
    for (int i = tid; i < 5 * 256 * 2; i += 320) {
        int arr = i >> 9, rem = i & 511, r = rem >> 1, col = rem & 1;
        int img = nc * AA + arr;
        d[arr * 2 + col][swz(brev9(128 + r))] =
            g_bufA[((size_t)img * HH + r) * HP + w0 + col];
    }
    __syncthreads();

    // forward DIT (ascending) -> natural frequency order
    #pragma unroll
    for (int p = 0; p < 3; p++) {
        for (int u = 0; u < 2; u++) {
            int wk = u * 320 + tid;              // 0..639
            int ac = wk >> 6, lane = wk & 63;
            reg_fft_phase(d[ac], p, lane, tw, 1.f, false);
        }
        __syncthreads();
    }

    // mix: G[b] = sum_a K[b][a][h][w] * F[a][h][w]
    for (int i = tid; i < 2 * 512; i += 320) {
        int col = i & 1, t = i >> 1;             // h = t natural, w = w0+col
        const float2* kp = g_kT + ((size_t)t * HP + w0 + col) * 25;
        float2 F[5], G[5];
        #pragma unroll
        for (int a2 = 0; a2 < 5; a2++) F[a2] = d[a2 * 2 + col][swz(t)];
        #pragma unroll
        for (int b = 0; b < 5; b++) {
            float2 acc = make_float2(0.f, 0.f);
            #pragma unroll
            for (int a2 = 0; a2 < 5; a2++) {
                float2 K = kp[b * 5 + a2];
                acc.x += K.x * F[a2].x - K.y * F[a2].y;
                acc.y += K.x * F[a2].y + K.y * F[a2].x;
            }
            G[b] = acc;
        }
        #pragma unroll
        for (int b = 0; b < 5; b++) d[b * 2 + col][swz(t)] = G[b];
    }
    __syncthreads();

    // inverse DIF (descending) -> time domain at bit-reversed positions
    #pragma unroll
    for (int p = 2; p >= 0; p--) {
        for (int u = 0; u < 2; u++) {
            int wk = u * 320 + tid;
            int ac = wk >> 6, lane = wk & 63;
            reg_fft_phase(d[ac], p, lane, tw, -1.f, true);
        }
        __syncthreads();
    }

    // cropped in-place write-back (rows 128..383), ortho scale 1/512
    const float sc = 1.0f / 512.0f;
    for (int i = tid; i < 5 * 256 * 2; i += 320) {
        int arr = i >> 9, rem = i & 511, r = rem >> 1, col = rem & 1;
        int img = nc * AA + arr;
        float2 v = d[arr * 2 + col][swz(brev9(128 + r))];
        g_bufA[((size_t)img * HH + r) * HP + w0 + col] = make_float2(v.x * sc, v.y * sc);
    }
}

// ---------------------------------------------------------------------------
// k_i2: inverse row FFTs (natural freq in -> DIF, isign=-1 -> bitrev out),
// crop cols, conj(mps) coil-combine over 12 coils. Block = (n,b,4 rows).
// ---------------------------------------------------------------------------
__global__ void __launch_bounds__(256)
k_i2(const float* __restrict__ mr, const float* __restrict__ mi,
     float* __restrict__ out, long out_floats) {
    __shared__ float2 d[4][512];
    __shared__ float2 tw[256];
    int tid = threadIdx.x;
    { float sv, cv; sincospif(-(float)tid / 256.0f, &sv, &cv); tw[tid] = make_float2(cv, sv); }

    int bid = blockIdx.x;
    int rg = bid & 63;
    int nb = bid >> 6;
    int b = nb % AA;
    int n = nb / AA;
    int row0 = rg * 4;

    float2 acc[4];
    #pragma unroll
    for (int r = 0; r < 4; r++) acc[r] = make_float2(0.f, 0.f);

    int row = tid >> 6, lane = tid & 63;

    for (int c = 0; c < CC; c++) {
        int img = (n * CC + c) * AA + b;
        __syncthreads();   // previous iteration's reads done before overwrite
        const float2* in = g_bufA + ((size_t)img * HH + row0) * HP;
        for (int i = tid; i < 4 * 512; i += 256) {
            int r = i >> 9, t = i & 511;
            d[r][swz(t)] = in[(size_t)r * HP + t];
        }
        __syncthreads();

        reg_fft_phase(d[row], 2, lane, tw, -1.f, true); __syncthreads();
        reg_fft_phase(d[row], 1, lane, tw, -1.f, true); __syncthreads();
        reg_fft_phase(d[row], 0, lane, tw, -1.f, true); __syncthreads();

        // crop col: output col = tid, padded index 128+tid, value at brev9
        #pragma unroll
        for (int r = 0; r < 4; r++) {
            float2 v = d[r][swz(brev9(128 + tid))];
            size_t mo = ((size_t)c * HH + row0 + r) * HH + tid;
            float m_r = mr[mo], m_i = mi[mo];
            acc[r].x += v.x * m_r + v.y * m_i;   // v * conj(m)
            acc[r].y += v.y * m_r - v.x * m_i;
        }
    }

    const float sc = 4.0f / 512.0f;
    #pragma unroll
    for (int r = 0; r < 4; r++) {
        size_t o = ((size_t)(n * AA + b) * HH + row0 + r) * HH + tid;
        if ((long)o < out_floats) out[o] = acc[r].x * sc;                 // real plane
        if ((long)(SZ_X + o) < out_floats) out[SZ_X + o] = acc[r].y * sc; // imag if room
    }
}

// ---------------------------------------------------------------------------
// Input resolver (identical to R7-passing version)
// ---------------------------------------------------------------------------
static void pick(void* const* d_in, const int* in_sizes, int n_in, long S,
                 int pos_split, const float** re, const float** im) {
    int idx[2] = {-1, -1};
    int cnt = 0;
    for (int i = 0; i < n_in; i++) {
        long v = (long)in_sizes[i];
        if (v == S || v == 2 * S || v == 4 * S || v == 8 * S) {
            if (cnt < 2) idx[cnt] = i;
            cnt++;
        }
    }
    if (cnt >= 2) {
        *re = (const float*)d_in[idx[0]];
        *im = (const float*)d_in[idx[1]];
    } else if (cnt == 1) {
        *re = (const float*)d_in[idx[0]];
        *im = *re + 1;
    } else {
        int p0 = (pos_split < n_in) ? pos_split : 0;
        int p1 = (pos_split + 1 < n_in) ? pos_split + 1 : p0;
        *re = (const float*)d_in[p0];
        *im = (const float*)d_in[p1];
    }
}

extern "C" void kernel_launch(void* const* d_in, const int* in_sizes, int n_in,
                              void* d_out, int out_size) {
    const float *xr, *xi, *mr, *mi, *kr, *ki;
    pick(d_in, in_sizes, n_in, SZ_X, 0, &xr, &xi);
    pick(d_in, in_sizes, n_in, SZ_M, 2, &mr, &mi);
    pick(d_in, in_sizes, n_in, SZ_K, 4, &kr, &ki);
    float* out = (float*)d_out;

    k_tr<<<NPIX / 256, 256>>>(kr, ki);
    k_f1<<<NIMG * 64, 256>>>(xr, xi, mr, mi);
    k_fused<<<(NN * CC) * (HP / 2), 320>>>();
    k_i2<<<NN * AA * 64, 256>>>(mr, mi, out, (long)out_size);
}

// round 10
// speedup vs baseline: 1.5217x; 1.2232x over previous
#include <cuda_runtime.h>
#include <cstdint>

#define NN 2
#define CC 12
#define AA 5
#define HH 256
#define HP 512
#define NIMG (NN*CC*AA)         // 120
#define NPIX (HP*HP)            // 262144
#define PH 576                  // padded smem line (512 + 512/8)

#define SZ_X ((long)NN*AA*HH*HH)   // 655360
#define SZ_M ((long)CC*HH*HH)      // 786432
#define SZ_K ((long)AA*AA*HP*HP)   // 6553600

// Scratch: 126MB + 52.4MB = 178.4MB (< ~190MB module limit from R1-R4)
// g_bufA layout: [img][w 512][r 256]  (transposed; float4-accessed)
__device__ __align__(128) float2 g_bufA[(size_t)NIMG * HP * HH];
// g_kT layout: [ba 25][w 512][h 512]  (SoA; coalesced mix reads)
__device__ __align__(128) float2 g_kT[(size_t)25 * NPIX];

__device__ __forceinline__ int brev9(int i) { return (int)(__brev((unsigned)i) >> 23); }
__device__ __forceinline__ int phys(int e)  { return e + (e >> 3); }   // pad swizzle

// ---------------------------------------------------------------------------
// Radix-8 register phase (validated R9 network; only smem indexing changed).
// tw[t] = exp(-i*pi*t/256). isign=+1: forward (negative exponent, numpy);
// isign=-1: inverse. dif=false: DIT ascending; dif=true: DIF descending.
// ---------------------------------------------------------------------------
__device__ __forceinline__ void reg_fft_phase(float2* a, int p, int lane,
                                              const float2* tw, float isign, bool dif) {
    int str, base;
    if (p == 0)      { str = 1;  base = lane << 3; }
    else if (p == 1) { str = 8;  base = ((lane >> 3) << 6) | (lane & 7); }
    else             { str = 64; base = lane; }
    int b_lo = base & (str - 1);

    float2 r[8];
    #pragma unroll
    for (int m = 0; m < 8; m++) r[m] = a[phys(base + m * str)];

    #pragma unroll
    for (int ss = 0; ss < 3; ss++) {
        int sub = dif ? (2 - ss) : ss;
        int s = 3 * p + sub + 1;          // global stage 1..9
        int half_m = 1 << sub;
        #pragma unroll
        for (int q = 0; q < 4; q++) {
            int jm = q & (half_m - 1);
            int m0 = ((q ^ jm) << 1) + jm;
            int m1 = m0 + half_m;
            int j = jm * str + b_lo;
            float2 w = tw[(j << (9 - s)) & 255];
            w.y *= isign;
            float2 A = r[m0], B = r[m1];
            if (!dif) {
                float2 t = make_float2(B.x * w.x - B.y * w.y, B.x * w.y + B.y * w.x);
                r[m0] = make_float2(A.x + t.x, A.y + t.y);
                r[m1] = make_float2(A.x - t.x, A.y - t.y);
            } else {
                float2 d = make_float2(A.x - B.x, A.y - B.y);
                r[m0] = make_float2(A.x + B.x, A.y + B.y);
                r[m1] = make_float2(d.x * w.x - d.y * w.y, d.x * w.y + d.y * w.x);
            }
        }
    }
    #pragma unroll
    for (int m = 0; m < 8; m++) a[phys(base + m * str)] = r[m];
}

// ---------------------------------------------------------------------------
// k_tr: tiled transpose kernels[ba][h][w] -> g_kT[ba][w][h]. 32x32 tiles.
// ---------------------------------------------------------------------------
__global__ void __launch_bounds__(256)
k_tr(const float* __restrict__ kr, const float* __restrict__ ki) {
    __shared__ float2 t[32][33];
    int ba = blockIdx.z;
    int tx = threadIdx.x & 31, ty = threadIdx.x >> 5;   // 32 x 8
    int h0 = blockIdx.y * 32, w0 = blockIdx.x * 32;
    #pragma unroll
    for (int k = 0; k < 4; k++) {
        size_t o = (size_t)ba * NPIX + (size_t)(h0 + ty + k * 8) * HP + w0 + tx;
        t[ty + k * 8][tx] = make_float2(kr[o], ki[o]);
    }
    __syncthreads();
    #pragma unroll
    for (int k = 0; k < 4; k++) {
        g_kT[(size_t)ba * NPIX + (size_t)(w0 + ty + k * 8) * HP + h0 + tx] = t[tx][ty + k * 8];
    }
}

// ---------------------------------------------------------------------------
// k_f1: row FFTs of padded x*mps. Block = (img, 4 rows), 256 thr.
// Output TRANSPOSED: g_bufA[img][w][r] via 32B float4 stores.
// ---------------------------------------------------------------------------
__global__ void __launch_bounds__(256)
k_f1(const float* __restrict__ xr, const float* __restrict__ xi,
     const float* __restrict__ mr, const float* __restrict__ mi) {
    __shared__ float2 d[4][PH];
    __shared__ float2 tw[256];
    int tid = threadIdx.x;
    { float sv, cv; sincospif(-(float)tid / 256.0f, &sv, &cv); tw[tid] = make_float2(cv, sv); }

    int img = blockIdx.x >> 6;
    int row0 = (blockIdx.x & 63) * 4;
    int a = img % AA, nc = img / AA, c = nc % CC, n = nc / CC;

    for (int i = tid; i < 4 * PH; i += 256) ((float2*)d)[i] = make_float2(0.f, 0.f);
    __syncthreads();

    for (int i = tid; i < 4 * 256; i += 256) {
        int r = i >> 8, iw = i & 255;
        size_t xo = ((size_t)(n * AA + a) * HH + row0 + r) * HH + iw;
        size_t mo = ((size_t)c * HH + row0 + r) * HH + iw;
        float ar = xr[xo], ai = xi[xo], br = mr[mo], bi = mi[mo];
        d[r][phys(brev9(128 + iw))] = make_float2(ar * br - ai * bi, ar * bi + ai * br);
    }
    __syncthreads();

    int row = tid >> 6, lane = tid & 63;
    reg_fft_phase(d[row], 0, lane, tw, 1.f, false); __syncthreads();
    reg_fft_phase(d[row], 1, lane, tw, 1.f, false); __syncthreads();
    reg_fft_phase(d[row], 2, lane, tw, 1.f, false); __syncthreads();

    // store transposed: thread per w, 32B contiguous (4 float2)
    for (int w = tid; w < 512; w += 256) {
        float2 v0 = d[0][phys(w)], v1 = d[1][phys(w)];
        float2 v2 = d[2][phys(w)], v3 = d[3][phys(w)];
        float4* p = (float4*)&g_bufA[((size_t)img * HP + w) * HH + row0];
        p[0] = make_float4(v0.x, v0.y, v1.x, v1.y);
        p[1] = make_float4(v2.x, v2.y, v3.x, v3.y);
    }
}

// ---------------------------------------------------------------------------
// k_fused: per (nc, 2-w tile): forward column FFT (zero-embed rows 128..383),
// 5x5 mix (SoA kT, coalesced), inverse FFT, cropped write-back. 640 threads.
// ---------------------------------------------------------------------------
__global__ void __launch_bounds__(640)
k_fused() {
    __shared__ float2 d[10][PH];      // [arr*2+col][PH]
    __shared__ float2 tw[256];
    int tid = threadIdx.x;
    if (tid < 256) { float sv, cv; sincospif(-(float)tid / 256.0f, &sv, &cv); tw[tid] = make_float2(cv, sv); }

    int bid = blockIdx.x;
    int nc = bid % (NN * CC);
    int w0 = (bid / (NN * CC)) * 2;

    for (int i = tid; i < 10 * PH; i += 640) ((float2*)d)[i] = make_float2(0.f, 0.f);
    __syncthreads();

    // load: 10 (arr,col) x 256 r — contiguous global runs
    for (int i = tid; i < 10 * 256; i += 640) {
        int ac = i >> 8, r = i & 255;
        int arr = ac >> 1, col = ac & 1;
        int img = nc * AA + arr;
        d[ac][phys(brev9(128 + r))] = g_bufA[((size_t)img * HP + w0 + col) * HH + r];
    }
    __syncthreads();

    int ac = tid >> 6, lane = tid & 63;

    // forward DIT -> natural frequency order
    reg_fft_phase(d[ac], 0, lane, tw, 1.f, false); __syncthreads();
    reg_fft_phase(d[ac], 1, lane, tw, 1.f, false); __syncthreads();
    reg_fft_phase(d[ac], 2, lane, tw, 1.f, false); __syncthreads();

    // mix: G[b](h,w) = sum_a K[b][a](h,w) * F[a](h,w); kT SoA coalesced
    for (int i = tid; i < 2 * 512; i += 640) {
        int col = i >> 9, t = i & 511;
        size_t kbase = (size_t)(w0 + col) * HP + t;
        float2 F[5], G[5];
        #pragma unroll
        for (int a2 = 0; a2 < 5; a2++) F[a2] = d[a2 * 2 + col][phys(t)];
        #pragma unroll
        for (int b = 0; b < 5; b++) {
            float2 acc = make_float2(0.f, 0.f);
            #pragma unroll
            for (int a2 = 0; a2 < 5; a2++) {
                float2 K = g_kT[(size_t)(b * 5 + a2) * NPIX + kbase];
                acc.x += K.x * F[a2].x - K.y * F[a2].y;
                acc.y += K.x * F[a2].y + K.y * F[a2].x;
            }
            G[b] = acc;
        }
        #pragma unroll
        for (int b = 0; b < 5; b++) d[b * 2 + col][phys(t)] = G[b];
    }
    __syncthreads();

    // inverse DIF -> time domain at bit-reversed positions
    reg_fft_phase(d[ac], 2, lane, tw, -1.f, true); __syncthreads();
    reg_fft_phase(d[ac], 1, lane, tw, -1.f, true); __syncthreads();
    reg_fft_phase(d[ac], 0, lane, tw, -1.f, true); __syncthreads();

    // cropped write-back (rows 128..383), ortho scale 1/512
    const float sc = 1.0f / 512.0f;
    for (int i = tid; i < 10 * 256; i += 640) {
        int ac2 = i >> 8, r = i & 255;
        int arr = ac2 >> 1, col = ac2 & 1;
        int img = nc * AA + arr;
        float2 v = d[ac2][phys(brev9(128 + r))];
        g_bufA[((size_t)img * HP + w0 + col) * HH + r] = make_float2(v.x * sc, v.y * sc);
    }
}

// ---------------------------------------------------------------------------
// k_i2: inverse row FFTs (transposed float4 loads), crop cols, conj(mps)
// coil-combine over 12 coils. Block = (n, b, 4 rows), 256 thr.
// ---------------------------------------------------------------------------
__global__ void __launch_bounds__(256)
k_i2(const float* __restrict__ mr, const float* __restrict__ mi,
     float* __restrict__ out, long out_floats) {
    __shared__ float2 d[4][PH];
    __shared__ float2 tw[256];
    int tid = threadIdx.x;
    { float sv, cv; sincospif(-(float)tid / 256.0f, &sv, &cv); tw[tid] = make_float2(cv, sv); }

    int bid = blockIdx.x;
    int row0 = (bid & 63) * 4;
    int nb = bid >> 6;
    int b = nb % AA;
    int n = nb / AA;

    float2 acc[4];
    #pragma unroll
    for (int r = 0; r < 4; r++) acc[r] = make_float2(0.f, 0.f);

    int row = tid >> 6, lane = tid & 63;

    for (int c = 0; c < CC; c++) {
        int img = (n * CC + c) * AA + b;
        __syncthreads();   // previous iteration's reads complete before overwrite
        for (int w = tid; w < 512; w += 256) {
            const float4* p = (const float4*)&g_bufA[((size_t)img * HP + w) * HH + row0];
            float4 q0 = p[0], q1 = p[1];
            d[0][phys(w)] = make_float2(q0.x, q0.y);
            d[1][phys(w)] = make_float2(q0.z, q0.w);
            d[2][phys(w)] = make_float2(q1.x, q1.y);
            d[3][phys(w)] = make_float2(q1.z, q1.w);
        }
        __syncthreads();

        reg_fft_phase(d[row], 2, lane, tw, -1.f, true); __syncthreads();
        reg_fft_phase(d[row], 1, lane, tw, -1.f, true); __syncthreads();
        reg_fft_phase(d[row], 0, lane, tw, -1.f, true); __syncthreads();

        #pragma unroll
        for (int r = 0; r < 4; r++) {
            float2 v = d[r][phys(brev9(128 + tid))];
            size_t mo = ((size_t)c * HH + row0 + r) * HH + tid;
            float m_r = mr[mo], m_i = mi[mo];
            acc[r].x += v.x * m_r + v.y * m_i;   // v * conj(m)
            acc[r].y += v.y * m_r - v.x * m_i;
        }
    }

    const float sc = 4.0f / 512.0f;
    #pragma unroll
    for (int r = 0; r < 4; r++) {
        size_t o = ((size_t)(n * AA + b) * HH + row0 + r) * HH + tid;
        if ((long)o < out_floats) out[o] = acc[r].x * sc;                 // real plane
        if ((long)(SZ_X + o) < out_floats) out[SZ_X + o] = acc[r].y * sc; // imag if room
    }
}

// ---------------------------------------------------------------------------
// Input resolver (identical to R7/R9-passing version)
// ---------------------------------------------------------------------------
static void pick(void* const* d_in, const int* in_sizes, int n_in, long S,
                 int pos_split, const float** re, const float** im) {
    int idx[2] = {-1, -1};
    int cnt = 0;
    for (int i = 0; i < n_in; i++) {
        long v = (long)in_sizes[i];
        if (v == S || v == 2 * S || v == 4 * S || v == 8 * S) {
            if (cnt < 2) idx[cnt] = i;
            cnt++;
        }
    }
    if (cnt >= 2) {
        *re = (const float*)d_in[idx[0]];
        *im = (const float*)d_in[idx[1]];
    } else if (cnt == 1) {
        *re = (const float*)d_in[idx[0]];
        *im = *re + 1;
    } else {
        int p0 = (pos_split < n_in) ? pos_split : 0;
        int p1 = (pos_split + 1 < n_in) ? pos_split + 1 : p0;
        *re = (const float*)d_in[p0];
        *im = (const float*)d_in[p1];
    }
}

extern "C" void kernel_launch(void* const* d_in, const int* in_sizes, int n_in,
                              void* d_out, int out_size) {
    const float *xr, *xi, *mr, *mi, *kr, *ki;
    pick(d_in, in_sizes, n_in, SZ_X, 0, &xr, &xi);
    pick(d_in, in_sizes, n_in, SZ_M, 2, &mr, &mi);
    pick(d_in, in_sizes, n_in, SZ_K, 4, &kr, &ki);
    float* out = (float*)d_out;

    dim3 trg(16, 16, 25);
    k_tr<<<trg, 256>>>(kr, ki);
    k_f1<<<NIMG * 64, 256>>>(xr, xi, mr, mi);
    k_fused<<<(NN * CC) * (HP / 2), 640>>>();
    k_i2<<<NN * AA * 64, 256>>>(mr, mi, out, (long)out_size);
}

// round 12
// speedup vs baseline: 2.1169x; 1.3912x over previous
#include <cuda_runtime.h>
#include <cstdint>

#define NN 2
#define CC 12
#define AA 5
#define HH 256
#define HP 512
#define NIMG (NN*CC*AA)         // 120
#define NPIX (HP*HP)            // 262144
#define PH 576                  // padded smem line (512 + 512/8)

#define SZ_X ((long)NN*AA*HH*HH)   // 655360
#define SZ_M ((long)CC*HH*HH)      // 786432
#define SZ_K ((long)AA*AA*HP*HP)   // 6553600

// Scratch: 126MB + 52.4MB = 178.4MB (< ~190MB module limit from R1-R4)
__device__ __align__(128) float2 g_bufA[(size_t)NIMG * HP * HH];  // [img][w][r]
__device__ __align__(128) float2 g_kT[(size_t)25 * NPIX];         // [ba][w][h]

__device__ __forceinline__ int brev9(int i) { return (int)(__brev((unsigned)i) >> 23); }
__device__ __forceinline__ int phys(int e)  { return e + (e >> 3); }

// 2-warp named barrier: syncs the 64-thread group owning one FFT array.
#define BAR64(id) asm volatile("bar.sync %0, 64;" :: "r"(id) : "memory")

// ---------------------------------------------------------------------------
// Radix-8 register phase, compile-time P (0,1,2) and DIF.
// tw[t] = exp(-i*pi*t/256). isign=+1 forward (numpy), -1 inverse.
// P=0 first sub-stage: w == 1 -> twiddle-free butterflies.
// ---------------------------------------------------------------------------
template<int P, bool DIF>
__device__ __forceinline__ void reg_fft_phase(float2* a, int lane,
                                              const float2* tw, float isign) {
    constexpr int str = (P == 0) ? 1 : ((P == 1) ? 8 : 64);
    int base;
    if (P == 0)      base = lane << 3;
    else if (P == 1) base = ((lane >> 3) << 6) | (lane & 7);
    else             base = lane;
    int b_lo = base & (str - 1);

    float2 r[8];
    #pragma unroll
    for (int m = 0; m < 8; m++) r[m] = a[phys(base + m * str)];

    #pragma unroll
    for (int ss = 0; ss < 3; ss++) {
        const int sub = DIF ? (2 - ss) : ss;
        const int s = 3 * P + sub + 1;          // global stage 1..9
        const int half_m = 1 << sub;
        #pragma unroll
        for (int q = 0; q < 4; q++) {
            int jm = q & (half_m - 1);
            int m0 = ((q ^ jm) << 1) + jm;
            int m1 = m0 + half_m;
            float2 A = r[m0], B = r[m1];
            if (P == 0 && sub == 0) {           // w == 1 (DIT==DIF)
                r[m0] = make_float2(A.x + B.x, A.y + B.y);
                r[m1] = make_float2(A.x - B.x, A.y - B.y);
            } else {
                int j = jm * str + b_lo;
                float2 w = tw[(j << (9 - s)) & 255];
                w.y *= isign;
                if (!DIF) {
                    float2 t = make_float2(B.x * w.x - B.y * w.y, B.x * w.y + B.y * w.x);
                    r[m0] = make_float2(A.x + t.x, A.y + t.y);
                    r[m1] = make_float2(A.x - t.x, A.y - t.y);
                } else {
                    float2 d = make_float2(A.x - B.x, A.y - B.y);
                    r[m0] = make_float2(A.x + B.x, A.y + B.y);
                    r[m1] = make_float2(d.x * w.x - d.y * w.y, d.x * w.y + d.y * w.x);
                }
            }
        }
    }
    #pragma unroll
    for (int m = 0; m < 8; m++) a[phys(base + m * str)] = r[m];
}

// ---------------------------------------------------------------------------
// k_tr: tiled transpose kernels[ba][h][w] -> g_kT[ba][w][h]
// ---------------------------------------------------------------------------
__global__ void __launch_bounds__(256)
k_tr(const float* __restrict__ kr, const float* __restrict__ ki) {
    __shared__ float2 t[32][33];
    int ba = blockIdx.z;
    int tx = threadIdx.x & 31, ty = threadIdx.x >> 5;
    int h0 = blockIdx.y * 32, w0 = blockIdx.x * 32;
    #pragma unroll
    for (int k = 0; k < 4; k++) {
        size_t o = (size_t)ba * NPIX + (size_t)(h0 + ty + k * 8) * HP + w0 + tx;
        t[ty + k * 8][tx] = make_float2(kr[o], ki[o]);
    }
    __syncthreads();
    #pragma unroll
    for (int k = 0; k < 4; k++) {
        g_kT[(size_t)ba * NPIX + (size_t)(w0 + ty + k * 8) * HP + h0 + tx] = t[tx][ty + k * 8];
    }
}

// ---------------------------------------------------------------------------
// k_f1: row FFTs of padded x*mps. Block = (img, 4 rows). Group-local IO.
// Output transposed g_bufA[img][w][r] via float4.
// ---------------------------------------------------------------------------
__global__ void __launch_bounds__(256)
k_f1(const float* __restrict__ xr, const float* __restrict__ xi,
     const float* __restrict__ mr, const float* __restrict__ mi) {
    __shared__ float2 d[4][PH];
    __shared__ float2 tw[256];
    int tid = threadIdx.x;
    { float sv, cv; sincospif(-(float)tid / 256.0f, &sv, &cv); tw[tid] = make_float2(cv, sv); }

    int img = blockIdx.x >> 6;
    int row0 = (blockIdx.x & 63) * 4;
    int a = img % AA, nc = img / AA, c = nc % CC, n = nc / CC;
    int row = tid >> 6, lane = tid & 63;
    int bar = row + 1;

    // group-local zero, THEN barrier, THEN scatter-load (zero/scatter race fix)
    #pragma unroll
    for (int k = lane; k < PH; k += 64) d[row][k] = make_float2(0.f, 0.f);
    BAR64(bar);   // both warps of the group finished zeroing before any scatter
    size_t xoff = ((size_t)(n * AA + a) * HH + row0 + row) * HH;
    size_t moff = ((size_t)c * HH + row0 + row) * HH;
    #pragma unroll
    for (int k = 0; k < 4; k++) {
        int iw = lane + k * 64;
        float ar = xr[xoff + iw], ai = xi[xoff + iw];
        float br = mr[moff + iw], bi = mi[moff + iw];
        d[row][phys(brev9(128 + iw))] = make_float2(ar * br - ai * bi, ar * bi + ai * br);
    }
    __syncthreads();   // tw visibility + own-array writes done

    reg_fft_phase<0,false>(d[row], lane, tw, 1.f); BAR64(bar);
    reg_fft_phase<1,false>(d[row], lane, tw, 1.f); BAR64(bar);
    reg_fft_phase<2,false>(d[row], lane, tw, 1.f);
    __syncthreads();   // store reads all arrays

    for (int w = tid; w < 512; w += 256) {
        float2 v0 = d[0][phys(w)], v1 = d[1][phys(w)];
        float2 v2 = d[2][phys(w)], v3 = d[3][phys(w)];
        float4* p = (float4*)&g_bufA[((size_t)img * HP + w) * HH + row0];
        p[0] = make_float4(v0.x, v0.y, v1.x, v1.y);
        p[1] = make_float4(v2.x, v2.y, v3.x, v3.y);
    }
}

// ---------------------------------------------------------------------------
// k_fused: forward col FFT + 5x5 mix + inverse col FFT per (nc, 2-w tile).
// 640 thr; 10 groups of 64, group-local IO, pair-synced FFT phases.
// ---------------------------------------------------------------------------
__global__ void __launch_bounds__(640, 2)
k_fused() {
    __shared__ float2 d[10][PH];
    __shared__ float2 tw[256];
    int tid = threadIdx.x;
    if (tid < 256) { float sv, cv; sincospif(-(float)tid / 256.0f, &sv, &cv); tw[tid] = make_float2(cv, sv); }

    int bid = blockIdx.x;
    int nc = bid % (NN * CC);
    int w0 = (bid / (NN * CC)) * 2;

    int ac = tid >> 6, lane = tid & 63;
    int arr = ac >> 1, col = ac & 1;
    int img = nc * AA + arr;
    int bar = ac + 1;

    // group-local zero, THEN barrier, THEN scatter-load (zero/scatter race fix)
    #pragma unroll
    for (int k = lane; k < PH; k += 64) d[ac][k] = make_float2(0.f, 0.f);
    BAR64(bar);   // both warps of the group finished zeroing before any scatter
    const float2* in = &g_bufA[((size_t)img * HP + w0 + col) * HH];
    #pragma unroll
    for (int k = 0; k < 4; k++) {
        int r = lane + k * 64;
        d[ac][phys(brev9(128 + r))] = in[r];
    }
    __syncthreads();   // tw visibility

    reg_fft_phase<0,false>(d[ac], lane, tw, 1.f); BAR64(bar);
    reg_fft_phase<1,false>(d[ac], lane, tw, 1.f); BAR64(bar);
    reg_fft_phase<2,false>(d[ac], lane, tw, 1.f);
    __syncthreads();   // mix reads all arrays

    // mix: G[b](h,w) = sum_a K[b][a](h,w) * F[a](h,w)
    for (int i = tid; i < 2 * 512; i += 640) {
        int mcol = i >> 9, t = i & 511;
        size_t kbase = (size_t)(w0 + mcol) * HP + t;
        float2 F[5], G[5];
        #pragma unroll
        for (int a2 = 0; a2 < 5; a2++) F[a2] = d[a2 * 2 + mcol][phys(t)];
        #pragma unroll
        for (int b = 0; b < 5; b++) {
            float2 acc = make_float2(0.f, 0.f);
            #pragma unroll
            for (int a2 = 0; a2 < 5; a2++) {
                float2 K = g_kT[(size_t)(b * 5 + a2) * NPIX + kbase];
                acc.x += K.x * F[a2].x - K.y * F[a2].y;
                acc.y += K.x * F[a2].y + K.y * F[a2].x;
            }
            G[b] = acc;
        }
        #pragma unroll
        for (int b = 0; b < 5; b++) d[b * 2 + mcol][phys(t)] = G[b];
    }
    __syncthreads();   // inverse reads own array, written by any thread

    reg_fft_phase<2,true>(d[ac], lane, tw, -1.f); BAR64(bar);
    reg_fft_phase<1,true>(d[ac], lane, tw, -1.f); BAR64(bar);
    reg_fft_phase<0,true>(d[ac], lane, tw, -1.f); BAR64(bar);

    // group-local cropped store, ortho scale 1/512
    const float sc = 1.0f / 512.0f;
    float2* outp = &g_bufA[((size_t)img * HP + w0 + col) * HH];
    #pragma unroll
    for (int k = 0; k < 4; k++) {
        int r = lane + k * 64;
        float2 v = d[ac][phys(brev9(128 + r))];
        outp[r] = make_float2(v.x * sc, v.y * sc);
    }
}

// ---------------------------------------------------------------------------
// k_i2: inverse row FFTs + crop + conj(mps) coil-combine. Block=(n,b,4 rows).
// Group-local accumulation: group=row, lane owns cols {lane+64k}.
// (No zero pass here: loads write all 512 logical slots — no race.)
// ---------------------------------------------------------------------------
__global__ void __launch_bounds__(256)
k_i2(const float* __restrict__ mr, const float* __restrict__ mi,
     float* __restrict__ out, long out_floats) {
    __shared__ float2 d[4][PH];
    __shared__ float2 tw[256];
    int tid = threadIdx.x;
    { float sv, cv; sincospif(-(float)tid / 256.0f, &sv, &cv); tw[tid] = make_float2(cv, sv); }

    int bid = blockIdx.x;
    int row0 = (bid & 63) * 4;
    int nb = bid >> 6;
    int b = nb % AA;
    int n = nb / AA;

    int row = tid >> 6, lane = tid & 63;
    int bar = row + 1;

    float2 acc[4];
    #pragma unroll
    for (int k = 0; k < 4; k++) acc[k] = make_float2(0.f, 0.f);

    for (int c = 0; c < CC; c++) {
        int img = (n * CC + c) * AA + b;
        __syncthreads();   // prior accum reads done (also tw on first iter)
        for (int w = tid; w < 512; w += 256) {
            const float4* p = (const float4*)&g_bufA[((size_t)img * HP + w) * HH + row0];
            float4 q0 = p[0], q1 = p[1];
            d[0][phys(w)] = make_float2(q0.x, q0.y);
            d[1][phys(w)] = make_float2(q0.z, q0.w);
            d[2][phys(w)] = make_float2(q1.x, q1.y);
            d[3][phys(w)] = make_float2(q1.z, q1.w);
        }
        __syncthreads();   // all-array writes visible

        reg_fft_phase<2,true>(d[row], lane, tw, -1.f); BAR64(bar);
        reg_fft_phase<1,true>(d[row], lane, tw, -1.f); BAR64(bar);
        reg_fft_phase<0,true>(d[row], lane, tw, -1.f); BAR64(bar);

        size_t moff = ((size_t)c * HH + row0 + row) * HH;
        #pragma unroll
        for (int k = 0; k < 4; k++) {
            int cw = lane + k * 64;
            float2 v = d[row][phys(brev9(128 + cw))];
            float m_r = mr[moff + cw], m_i = mi[moff + cw];
            acc[k].x += v.x * m_r + v.y * m_i;   // v * conj(m)
            acc[k].y += v.y * m_r - v.x * m_i;
        }
    }

    const float sc = 4.0f / 512.0f;
    size_t obase = ((size_t)(n * AA + b) * HH + row0 + row) * HH;
    #pragma unroll
    for (int k = 0; k < 4; k++) {
        size_t o = obase + lane + k * 64;
        if ((long)o < out_floats) out[o] = acc[k].x * sc;                 // real plane
        if ((long)(SZ_X + o) < out_floats) out[SZ_X + o] = acc[k].y * sc; // imag if room
    }
}

// ---------------------------------------------------------------------------
// Input resolver (identical to R7/R9/R10-passing version)
// ---------------------------------------------------------------------------
static void pick(void* const* d_in, const int* in_sizes, int n_in, long S,
                 int pos_split, const float** re, const float** im) {
    int idx[2] = {-1, -1};
    int cnt = 0;
    for (int i = 0; i < n_in; i++) {
        long v = (long)in_sizes[i];
        if (v == S || v == 2 * S || v == 4 * S || v == 8 * S) {
            if (cnt < 2) idx[cnt] = i;
            cnt++;
        }
    }
    if (cnt >= 2) {
        *re = (const float*)d_in[idx[0]];
        *im = (const float*)d_in[idx[1]];
    } else if (cnt == 1) {
        *re = (const float*)d_in[idx[0]];
        *im = *re + 1;
    } else {
        int p0 = (pos_split < n_in) ? pos_split : 0;
        int p1 = (pos_split + 1 < n_in) ? pos_split + 1 : p0;
        *re = (const float*)d_in[p0];
        *im = (const float*)d_in[p1];
    }
}

extern "C" void kernel_launch(void* const* d_in, const int* in_sizes, int n_in,
                              void* d_out, int out_size) {
    const float *xr, *xi, *mr, *mi, *kr, *ki;
    pick(d_in, in_sizes, n_in, SZ_X, 0, &xr, &xi);
    pick(d_in, in_sizes, n_in, SZ_M, 2, &mr, &mi);
    pick(d_in, in_sizes, n_in, SZ_K, 4, &kr, &ki);
    float* out = (float*)d_out;

    dim3 trg(16, 16, 25);
    k_tr<<<trg, 256>>>(kr, ki);
    k_f1<<<NIMG * 64, 256>>>(xr, xi, mr, mi);
    k_fused<<<(NN * CC) * (HP / 2), 640>>>();
    k_i2<<<NN * AA * 64, 256>>>(mr, mi, out, (long)out_size);
}